// round 10
// baseline (speedup 1.0000x reference)
#include <cuda_runtime.h>
#include <cuda_fp16.h>
#include <cstdint>

// ---------------------------------------------------------------------------
// Problem constants
// ---------------------------------------------------------------------------
static constexpr int B_  = 4;
static constexpr int C_  = 64;
static constexpr int H_  = 256;
static constexpr int W_  = 512;
static constexpr int HW  = H_ * W_;               // 131072 = 2^17
static constexpr int SW_ = 3 * W_;                // 1536
static constexpr int TILE_P = 512;                // one full image row
static constexpr int TILES_PER_B = HW / TILE_P;   // 256
static constexpr int N_TILES = B_ * TILES_PER_B;  // 1024
static constexpr int THREADS = 256;               // 8 warps, 64 px/warp

// A stages: 512 px rows x 144B pitch (128B data + 16B pad, ldmatrix-friendly)
static constexpr int A_PITCH_B = 144;
static constexpr int A_BYTES   = TILE_P * A_PITCH_B;        // 73728
// W: [tap][co][ci] halves, 128B rows, chunk-XOR swizzled (conflict-free LDS)
static constexpr int W_TAP_B   = C_ * 128;                  // 8192
static constexpr int W_BYTES   = 9 * W_TAP_B;               // 73728

static constexpr int SMEM_W    = 0;
static constexpr int SMEM_BIAS = W_BYTES;                   // 256 B
static constexpr int SMEM_BAR  = W_BYTES + 256;             // 4 x 8B mbarriers
static constexpr int SMEM_A    = W_BYTES + 512;             // 74240 (128-aligned)
static constexpr int SMEM_TOTAL = SMEM_A + 2 * A_BYTES;     // 221696

__device__ int    g_idx_is64;
__device__ __align__(128) __half g_xt[(size_t)B_ * HW * C_];  // [B][HW][C] fp16

// ---------------------------------------------------------------------------
// PTX helpers
// ---------------------------------------------------------------------------
__device__ __forceinline__ uint32_t smem_u32(const void* p) {
    uint32_t a;
    asm("{ .reg .u64 t; cvta.to.shared.u64 t, %1; cvt.u32.u64 %0, t; }" : "=r"(a) : "l"(p));
    return a;
}

__device__ __forceinline__ void ldmatrix_x4(uint32_t* r, uint32_t addr) {
    asm volatile("ldmatrix.sync.aligned.m8n8.x4.shared.b16 {%0,%1,%2,%3}, [%4];"
                 : "=r"(r[0]), "=r"(r[1]), "=r"(r[2]), "=r"(r[3]) : "r"(addr));
}

__device__ __forceinline__ void mma_f16(float* c, const uint32_t* a, uint32_t b0, uint32_t b1) {
    asm volatile(
        "mma.sync.aligned.m16n8k16.row.col.f32.f16.f16.f32 "
        "{%0,%1,%2,%3}, {%4,%5,%6,%7}, {%8,%9}, {%0,%1,%2,%3};"
        : "+f"(c[0]), "+f"(c[1]), "+f"(c[2]), "+f"(c[3])
        : "r"(a[0]), "r"(a[1]), "r"(a[2]), "r"(a[3]), "r"(b0), "r"(b1));
}

#define MBARRIER_INIT(bar, cnt) \
    asm volatile("mbarrier.init.shared.b64 [%0], %1;" :: "r"(bar), "r"((uint32_t)(cnt)) : "memory")

// fused arrive + expect-tx (per issuing thread)
#define MBARRIER_EXPECT_TX(bar, bytes) \
    asm volatile("mbarrier.arrive.expect_tx.shared.b64 _, [%0], %1;" \
                 :: "r"(bar), "r"((uint32_t)(bytes)) : "memory")

#define MBARRIER_WAIT_PARITY(bar, ph) do {                                              \
    uint32_t _m = (bar); uint32_t _p = (ph); uint32_t _d;                               \
    asm volatile("{\n\t.reg .pred p;\n\t"                                               \
        "mbarrier.try_wait.parity.acquire.cta.shared::cta.b64 p, [%1], %2;\n\t"         \
        "selp.b32 %0, 1, 0, p;\n\t}" : "=r"(_d) : "r"(_m), "r"(_p) : "memory");         \
    if (!_d) {                                                                          \
        asm volatile("{\n\t.reg .pred P1;\n\t"                                          \
            "WL_%=:\n\t"                                                                \
            "mbarrier.try_wait.parity.acquire.cta.shared::cta.b64 P1, [%0], %1, 0x989680;\n\t" \
            "@P1 bra.uni WD_%=;\n\t"                                                    \
            "bra.uni WL_%=;\n\t"                                                        \
            "WD_%=:\n\t}" :: "r"(_m), "r"(_p) : "memory");                              \
    }                                                                                   \
} while (0)

// one 128-byte row: global -> shared, completion counted on mbar
__device__ __forceinline__ void bulk_row(uint32_t dst, const void* src, uint32_t mbar) {
    asm volatile(
        "cp.async.bulk.shared::cta.global.mbarrier::complete_tx::bytes [%0], [%1], 128, [%2];"
        :: "r"(dst), "l"(src), "r"(mbar) : "memory");
}

// ---------------------------------------------------------------------------
// Kernel 0: idx dtype detect
// ---------------------------------------------------------------------------
__global__ void detect_kernel(const unsigned int* __restrict__ w) {
    if (threadIdx.x == 0) {
        int is64 = 1;
        for (int i = 0; i < 64; ++i)
            if (w[2 * i + 1] != 0u) { is64 = 0; break; }
        g_idx_is64 = is64;
    }
}

// ---------------------------------------------------------------------------
// Kernel 1: transpose x [B][C][HW] -> g_xt [B][HW][C] fp16 (coalesced stores)
// ---------------------------------------------------------------------------
__global__ void transpose_kernel(const float* __restrict__ x) {
    __shared__ float t[32][33];
    const int b  = blockIdx.z;
    const int cb = blockIdx.y * 32;
    const int gb = blockIdx.x * 32;
    const int tx = threadIdx.x, ty = threadIdx.y;
    const float* xb = x + (size_t)b * C_ * HW;
#pragma unroll
    for (int i = 0; i < 32; i += 8)
        t[ty + i][tx] = xb[(size_t)(cb + ty + i) * HW + gb + tx];
    __syncthreads();
    __half* xtb = g_xt + ((size_t)b * HW) * C_;
    const int c2  = tx & 15;
    const int sel = tx >> 4;
#pragma unroll
    for (int i = 0; i < 2; ++i) {
        int hwl = ty * 4 + sel * 2 + i;
        __half2 v = __floats2half2_rn(t[2 * c2][hwl], t[2 * c2 + 1][hwl]);
        *(__half2*)(xtb + (size_t)(gb + hwl) * C_ + cb + 2 * c2) = v;
    }
}

// ---------------------------------------------------------------------------
// Kernel 2: persistent fused gather (cp.async.bulk, 2-stage x half-split
//           mbarrier ring) + fp16 mma.sync.  tile = 512 px x 64 co.
//           8 warps: warp w computes px [w*64, w*64+64) x all 64 co.
// ---------------------------------------------------------------------------
struct Cur { int tile; int tap; };
__device__ __forceinline__ void adv(Cur& c, int stride) {
    if (++c.tap == 9) { c.tap = 0; c.tile += stride; }
}

__device__ __forceinline__ int load_idx(const void* idx, int is64, const Cur& c, int p) {
    int pt = c.tile & (TILES_PER_B - 1);       // image row
    int kh = c.tap / 3;
    int kw = c.tap - kh * 3;
    int o  = (3 * pt + kh) * SW_ + 3 * p + kw;
    return is64 ? (int)((const long long*)idx)[o] : ((const int*)idx)[o];
}

__device__ __forceinline__ void issue_row(int tile, int g, int p,
                                          uint32_t stage_base, uint32_t mbar) {
    const char* src = (const char*)g_xt
                    + ((((size_t)(tile >> 8)) << 17) + (uint32_t)g) * (C_ * 2);
    bulk_row(stage_base + p * A_PITCH_B, src, mbar);
}

__global__ void __launch_bounds__(THREADS, 1)
latconv_main(const void* __restrict__ idx_raw,
             const float* __restrict__ wgt,
             const float* __restrict__ bias,
             float* __restrict__ out) {
    extern __shared__ char smem[];
    const uint32_t wbase = smem_u32(smem + SMEM_W);
    float* bsm = (float*)(smem + SMEM_BIAS);

    const int tid = threadIdx.x;
    const int wid = tid >> 5;       // 0..7
    const int lid = tid & 31;
    const int gid = lid >> 2;       // 0..7
    const int tig = lid & 3;        // 0..3
    const int is64 = g_idx_is64;

    // ldmatrix per-lane address constant (16x16 A tiles, 144B pitch)
    const int lm = lid >> 3, lr = lid & 7;
    const uint32_t lconst = (uint32_t)(((lm & 1) * 8 + lr) * A_PITCH_B
                                       + (lm >> 1) * 16 + wid * 64 * A_PITCH_B);

    // stage weights fp16, chunk-XOR swizzle: byte(j,co,ci) =
    //   j*8192 + co*128 + ((ci>>3)^(co&7))*16 + (ci&7)*2
    for (int e = tid; e < C_ * C_ * 9; e += THREADS) {
        int ci = e & 63, co = (e >> 6) & 63, j = e >> 12;
        uint32_t off = (uint32_t)(j * W_TAP_B + co * 128
                     + (((ci >> 3) ^ (co & 7)) << 4) + ((ci & 7) << 1));
        *(__half*)(smem + SMEM_W + off) = __float2half_rn(wgt[co * 576 + ci * 9 + j]);
    }
    if (tid < C_) bsm[tid] = bias[tid];

    const uint32_t barb   = smem_u32(smem + SMEM_BAR);
    const uint32_t abase0 = smem_u32(smem + SMEM_A);
    if (tid == 0) {
        // each of the THREADS threads does exactly ONE arrive.expect_tx per
        // half-barrier per phase -> arrive count = THREADS  (round-9 bug: 2x)
#pragma unroll
        for (int i = 0; i < 4; ++i) MBARRIER_INIT(barb + 8 * i, THREADS);
    }
    __syncthreads();

    const int nloc = (N_TILES - (int)blockIdx.x + (int)gridDim.x - 1) / (int)gridDim.x;
    const int S = nloc * 9;
    if (S == 0) return;

    const int whalf = wid >> 2;                // compute-wait half (0/1)

    // prologue: fill stage 0 (each thread issues rows tid (half0), tid+256 (half1))
    Cur c0 = {(int)blockIdx.x, 0};
    {
        int g0 = load_idx(idx_raw, is64, c0, tid);
        int g1 = load_idx(idx_raw, is64, c0, tid + 256);
        MBARRIER_EXPECT_TX(barb + 0, 128);
        issue_row(c0.tile, g0, tid, abase0, barb + 0);
        MBARRIER_EXPECT_TX(barb + 8, 128);
        issue_row(c0.tile, g1, tid + 256, abase0, barb + 8);
    }
    Cur c_iss = c0; adv(c_iss, gridDim.x);     // step 1
    int r0 = 0, r1 = 0;
    if (S > 1) {
        r0 = load_idx(idx_raw, is64, c_iss, tid);
        r1 = load_idx(idx_raw, is64, c_iss, tid + 256);
    }
    Cur c_pre = c_iss; adv(c_pre, gridDim.x);  // step 2

    Cur c_cmp = {(int)blockIdx.x, 0};
    int ph[2] = {0, 0};

    float acc[4][8][4];

    for (int s = 0; s < S; ++s) {
        __syncthreads();   // all warps finished step s-1 -> stage (s+1)&1 free

        if (s + 1 < S) {
            const int bi = (s + 1) & 1;
            MBARRIER_EXPECT_TX(barb + bi * 16 + 0, 128);
            issue_row(c_iss.tile, r0, tid, abase0 + bi * A_BYTES, barb + bi * 16 + 0);
            MBARRIER_EXPECT_TX(barb + bi * 16 + 8, 128);
            issue_row(c_iss.tile, r1, tid + 256, abase0 + bi * A_BYTES, barb + bi * 16 + 8);
        }
        if (s + 2 < S) {
            r0 = load_idx(idx_raw, is64, c_pre, tid);
            r1 = load_idx(idx_raw, is64, c_pre, tid + 256);
        }
        adv(c_iss, gridDim.x);
        adv(c_pre, gridDim.x);

        if (c_cmp.tap == 0) {
#pragma unroll
            for (int mh = 0; mh < 4; ++mh)
#pragma unroll
                for (int nt = 0; nt < 8; ++nt)
#pragma unroll
                    for (int q = 0; q < 4; ++q) acc[mh][nt][q] = 0.f;
        }

        // wait my half of current stage, then compute tap
        const int bc = s & 1;
        MBARRIER_WAIT_PARITY(barb + bc * 16 + whalf * 8, ph[bc]);
        ph[bc] ^= 1;

        {
            const uint32_t ab = abase0 + bc * A_BYTES;
            const uint32_t wb = wbase + (uint32_t)c_cmp.tap * W_TAP_B
                              + (uint32_t)gid * 128 + (uint32_t)tig * 4;
#pragma unroll
            for (int ks = 0; ks < 4; ++ks) {
                uint32_t a[4][4];
#pragma unroll
                for (int mh = 0; mh < 4; ++mh)
                    ldmatrix_x4(a[mh], ab + lconst + mh * (16 * A_PITCH_B) + ks * 32);
                const uint32_t c0off = (uint32_t)(((2 * ks)     ^ gid) << 4);
                const uint32_t c1off = (uint32_t)(((2 * ks + 1) ^ gid) << 4);
#pragma unroll
                for (int nt = 0; nt < 8; ++nt) {
                    uint32_t wrow = wb + nt * 1024;
                    uint32_t b0, b1;
                    asm volatile("ld.shared.b32 %0, [%1];" : "=r"(b0) : "r"(wrow + c0off));
                    asm volatile("ld.shared.b32 %0, [%1];" : "=r"(b1) : "r"(wrow + c1off));
#pragma unroll
                    for (int mh = 0; mh < 4; ++mh)
                        mma_f16(acc[mh][nt], a[mh], b0, b1);
                }
            }
        }

        if (c_cmp.tap == 8) {
            // epilogue: direct STG from accumulators
            int b  = c_cmp.tile >> 8;
            int pt = c_cmp.tile & (TILES_PER_B - 1);
            float* op = out + ((size_t)b << 23) + (size_t)pt * TILE_P;
#pragma unroll
            for (int mh = 0; mh < 4; ++mh) {
                int px = wid * 64 + mh * 16 + gid;
#pragma unroll
                for (int nt = 0; nt < 8; ++nt) {
                    int co = nt * 8 + 2 * tig;
                    float b0 = bsm[co], b1 = bsm[co + 1];
                    float* q = op + (size_t)co * HW + px;
                    q[0]      = acc[mh][nt][0] + b0;
                    q[HW]     = acc[mh][nt][1] + b1;
                    q[8]      = acc[mh][nt][2] + b0;
                    q[HW + 8] = acc[mh][nt][3] + b1;
                }
            }
        }

        adv(c_cmp, gridDim.x);
    }
}

// ---------------------------------------------------------------------------
// Launch
// ---------------------------------------------------------------------------
extern "C" void kernel_launch(void* const* d_in, const int* in_sizes, int n_in,
                              void* d_out, int out_size) {
    const float* x    = (const float*)d_in[0];
    const void*  idx  = d_in[1];
    const float* wgt  = (const float*)d_in[2];
    const float* bias = (const float*)d_in[3];
    float* out        = (float*)d_out;

    detect_kernel<<<1, 32>>>((const unsigned int*)idx);

    dim3 tb(32, 8);
    dim3 tg(HW / 32, C_ / 32, B_);
    transpose_kernel<<<tg, tb>>>(x);

    cudaFuncSetAttribute(latconv_main, cudaFuncAttributeMaxDynamicSharedMemorySize,
                         SMEM_TOTAL);
    int sm_count = 0;
    cudaDeviceGetAttribute(&sm_count, cudaDevAttrMultiProcessorCount, 0);
    if (sm_count <= 0) sm_count = 148;

    latconv_main<<<sm_count, THREADS, SMEM_TOTAL>>>(idx, wgt, bias, out);
}

// round 11
// speedup vs baseline: 1.2409x; 1.2409x over previous
#include <cuda_runtime.h>
#include <cuda_fp16.h>
#include <cstdint>

// ---------------------------------------------------------------------------
// Problem constants
// ---------------------------------------------------------------------------
static constexpr int B_  = 4;
static constexpr int C_  = 64;
static constexpr int H_  = 256;
static constexpr int W_  = 512;
static constexpr int HW  = H_ * W_;               // 131072 = 2^17
static constexpr int SW_ = 3 * W_;                // 1536
static constexpr int TILE_P = 512;                // one full image row
static constexpr int TILES_PER_B = HW / TILE_P;   // 256
static constexpr int N_TILES = B_ * TILES_PER_B;  // 1024
static constexpr int THREADS = 512;               // 16 warps, 32 px/warp

// A stages: 512 px rows x 144B pitch (128B data + 16B pad, ldmatrix-friendly)
static constexpr int A_PITCH_B = 144;
static constexpr int A_BYTES   = TILE_P * A_PITCH_B;        // 73728
// W: [tap][co][ci] halves, 128B rows, chunk-XOR swizzled (conflict-free LDS)
static constexpr int W_TAP_B   = C_ * 128;                  // 8192
static constexpr int W_BYTES   = 9 * W_TAP_B;               // 73728

static constexpr int SMEM_W    = 0;
static constexpr int SMEM_BIAS = W_BYTES;                   // 256 B
static constexpr int SMEM_A    = W_BYTES + 256;             // 73984 (128-aligned)
static constexpr int SMEM_TOTAL = SMEM_A + 2 * A_BYTES;     // 221440

__device__ int    g_idx_is64;
__device__ __align__(128) __half g_xt[(size_t)B_ * HW * C_];  // [B][HW][C] fp16

// ---------------------------------------------------------------------------
// PTX helpers
// ---------------------------------------------------------------------------
__device__ __forceinline__ uint32_t smem_u32(const void* p) {
    uint32_t a;
    asm("{ .reg .u64 t; cvta.to.shared.u64 t, %1; cvt.u32.u64 %0, t; }" : "=r"(a) : "l"(p));
    return a;
}

__device__ __forceinline__ void ldmatrix_x4(uint32_t* r, uint32_t addr) {
    asm volatile("ldmatrix.sync.aligned.m8n8.x4.shared.b16 {%0,%1,%2,%3}, [%4];"
                 : "=r"(r[0]), "=r"(r[1]), "=r"(r[2]), "=r"(r[3]) : "r"(addr));
}

__device__ __forceinline__ void mma_f16(float* c, const uint32_t* a, uint32_t b0, uint32_t b1) {
    asm volatile(
        "mma.sync.aligned.m16n8k16.row.col.f32.f16.f16.f32 "
        "{%0,%1,%2,%3}, {%4,%5,%6,%7}, {%8,%9}, {%0,%1,%2,%3};"
        : "+f"(c[0]), "+f"(c[1]), "+f"(c[2]), "+f"(c[3])
        : "r"(a[0]), "r"(a[1]), "r"(a[2]), "r"(a[3]), "r"(b0), "r"(b1));
}

__device__ __forceinline__ void sts128(uint32_t addr, float4 v) {
    asm volatile("st.shared.v4.b32 [%0], {%1,%2,%3,%4};"
                 :: "r"(addr), "f"(v.x), "f"(v.y), "f"(v.z), "f"(v.w) : "memory");
}

// ---------------------------------------------------------------------------
// Kernel 1: transpose x [B][C][HW] -> g_xt [B][HW][C] fp16; block (0,0,0)
//           also detects idx dtype (int64 vs int32).
// ---------------------------------------------------------------------------
__global__ void transpose_kernel(const float* __restrict__ x,
                                 const unsigned int* __restrict__ idxw) {
    if (blockIdx.x == 0 && blockIdx.y == 0 && blockIdx.z == 0 &&
        threadIdx.x == 0 && threadIdx.y == 0) {
        int is64 = 1;
        for (int i = 0; i < 64; ++i)
            if (idxw[2 * i + 1] != 0u) { is64 = 0; break; }
        g_idx_is64 = is64;
    }
    __shared__ float t[32][33];
    const int b  = blockIdx.z;
    const int cb = blockIdx.y * 32;
    const int gb = blockIdx.x * 32;
    const int tx = threadIdx.x, ty = threadIdx.y;
    const float* xb = x + (size_t)b * C_ * HW;
#pragma unroll
    for (int i = 0; i < 32; i += 8)
        t[ty + i][tx] = xb[(size_t)(cb + ty + i) * HW + gb + tx];
    __syncthreads();
    __half* xtb = g_xt + ((size_t)b * HW) * C_;
    const int c2  = tx & 15;
    const int sel = tx >> 4;
#pragma unroll
    for (int i = 0; i < 2; ++i) {
        int hwl = ty * 4 + sel * 2 + i;
        __half2 v = __floats2half2_rn(t[2 * c2][hwl], t[2 * c2 + 1][hwl]);
        *(__half2*)(xtb + (size_t)(gb + hwl) * C_ + cb + 2 * c2) = v;
    }
}

// ---------------------------------------------------------------------------
// Kernel 2: persistent fused gather (LDG.128 + STS.128, 2-stage ring,
//           software-pipelined within the step) + fp16 mma.sync.
//           tile = 512 px x 64 co.  16 warps: warp w owns px [w*32, w*32+32).
// ---------------------------------------------------------------------------
struct Cur { int tile; int tap; };
__device__ __forceinline__ void adv(Cur& c, int stride) {
    if (++c.tap == 9) { c.tap = 0; c.tile += stride; }
}

// gather one 16B chunk: row's idx -> xt row base + 16B lane chunk
__device__ __forceinline__ float4 gather16(const void* idx, int is64,
                                           const Cur& c, int row, int lane7) {
    int pt = c.tile & (TILES_PER_B - 1);       // image row
    int kh = c.tap / 3;
    int kw = c.tap - kh * 3;
    int o  = (3 * pt + kh) * SW_ + 3 * row + kw;
    int g  = is64 ? (int)__ldg((const long long*)idx + o)
                  : __ldg((const int*)idx + o);
    const char* src = (const char*)g_xt
                    + ((((size_t)(c.tile >> 8)) << 17) + (uint32_t)g) * (C_ * 2)
                    + lane7 * 16;
    return __ldg((const float4*)src);
}

__global__ void __launch_bounds__(THREADS, 1)
latconv_main(const void* __restrict__ idx_raw,
             const float* __restrict__ wgt,
             const float* __restrict__ bias,
             float* __restrict__ out) {
    extern __shared__ char smem[];
    const uint32_t wbase = smem_u32(smem + SMEM_W);
    float* bsm = (float*)(smem + SMEM_BIAS);

    const int tid = threadIdx.x;
    const int wid = tid >> 5;       // 0..15
    const int lid = tid & 31;
    const int gid = lid >> 2;       // 0..7
    const int tig = lid & 3;        // 0..3
    const int is64 = g_idx_is64;

    // gather lane mapping: 8 lanes per row -> each warp-LDG.128 covers 4 rows
    const int lane7 = lid & 7;
    const int rbase = wid * 32 + (lid >> 3);   // + k*4 for k = 0..7

    // ldmatrix per-lane address constant (16x16 A tiles, 144B pitch)
    const int lm = lid >> 3, lr = lid & 7;
    const uint32_t lconst = (uint32_t)(((lm & 1) * 8 + lr) * A_PITCH_B
                                       + (lm >> 1) * 16 + wid * 32 * A_PITCH_B);

    // stage weights fp16, chunk-XOR swizzle: byte(j,co,ci) =
    //   j*8192 + co*128 + ((ci>>3)^(co&7))*16 + (ci&7)*2
    for (int e = tid; e < C_ * C_ * 9; e += THREADS) {
        int ci = e & 63, co = (e >> 6) & 63, j = e >> 12;
        uint32_t off = (uint32_t)(j * W_TAP_B + co * 128
                     + (((ci >> 3) ^ (co & 7)) << 4) + ((ci & 7) << 1));
        *(__half*)(smem + SMEM_W + off) = __float2half_rn(wgt[co * 576 + ci * 9 + j]);
    }
    if (tid < C_) bsm[tid] = bias[tid];

    const uint32_t abase0 = smem_u32(smem + SMEM_A);

    const int nloc = (N_TILES - (int)blockIdx.x + (int)gridDim.x - 1) / (int)gridDim.x;
    const int S = nloc * 9;
    if (S == 0) return;

    // prologue: fill stage 0 with step-0 data
    Cur c0 = {(int)blockIdx.x, 0};
    {
#pragma unroll
        for (int k = 0; k < 8; ++k) {
            float4 v = gather16(idx_raw, is64, c0, rbase + k * 4, lane7);
            sts128(abase0 + (uint32_t)(rbase + k * 4) * A_PITCH_B + lane7 * 16, v);
        }
    }
    Cur c_iss = c0; adv(c_iss, gridDim.x);     // gathers for step s+1
    Cur c_cmp = {(int)blockIdx.x, 0};

    float acc[2][8][4];

    for (int s = 0; s < S; ++s) {
        __syncthreads();   // stage (s&1) writes visible; stage (s+1)&1 free

        const int  bc   = s & 1;
        const bool have = (s + 1 < S);
        const uint32_t ab = abase0 + bc * A_BYTES;
        const uint32_t an = abase0 + (bc ^ 1) * A_BYTES;

        // batch-A gather LDGs for step s+1 (held in regs through compute)
        float4 stg[4];
        if (have) {
#pragma unroll
            for (int k = 0; k < 4; ++k)
                stg[k] = gather16(idx_raw, is64, c_iss, rbase + k * 4, lane7);
        }

        if (c_cmp.tap == 0) {
#pragma unroll
            for (int mh = 0; mh < 2; ++mh)
#pragma unroll
                for (int nt = 0; nt < 8; ++nt)
#pragma unroll
                    for (int q = 0; q < 4; ++q) acc[mh][nt][q] = 0.f;
        }

        const uint32_t wb = wbase + (uint32_t)c_cmp.tap * W_TAP_B
                          + (uint32_t)gid * 128 + (uint32_t)tig * 4;

        // compute ks = 0,1
#pragma unroll
        for (int ks = 0; ks < 2; ++ks) {
            uint32_t a[2][4];
#pragma unroll
            for (int mh = 0; mh < 2; ++mh)
                ldmatrix_x4(a[mh], ab + lconst + mh * (16 * A_PITCH_B) + ks * 32);
            const uint32_t c0off = (uint32_t)(((2 * ks)     ^ gid) << 4);
            const uint32_t c1off = (uint32_t)(((2 * ks + 1) ^ gid) << 4);
#pragma unroll
            for (int nt = 0; nt < 8; ++nt) {
                uint32_t wrow = wb + nt * 1024;
                uint32_t b0, b1;
                asm volatile("ld.shared.b32 %0, [%1];" : "=r"(b0) : "r"(wrow + c0off));
                asm volatile("ld.shared.b32 %0, [%1];" : "=r"(b1) : "r"(wrow + c1off));
                mma_f16(acc[0][nt], a[0], b0, b1);
                mma_f16(acc[1][nt], a[1], b0, b1);
            }
        }

        // store batch A, launch batch B
        if (have) {
#pragma unroll
            for (int k = 0; k < 4; ++k)
                sts128(an + (uint32_t)(rbase + k * 4) * A_PITCH_B + lane7 * 16, stg[k]);
#pragma unroll
            for (int k = 0; k < 4; ++k)
                stg[k] = gather16(idx_raw, is64, c_iss, rbase + (k + 4) * 4, lane7);
        }

        // compute ks = 2,3
#pragma unroll
        for (int ks = 2; ks < 4; ++ks) {
            uint32_t a[2][4];
#pragma unroll
            for (int mh = 0; mh < 2; ++mh)
                ldmatrix_x4(a[mh], ab + lconst + mh * (16 * A_PITCH_B) + ks * 32);
            const uint32_t c0off = (uint32_t)(((2 * ks)     ^ gid) << 4);
            const uint32_t c1off = (uint32_t)(((2 * ks + 1) ^ gid) << 4);
#pragma unroll
            for (int nt = 0; nt < 8; ++nt) {
                uint32_t wrow = wb + nt * 1024;
                uint32_t b0, b1;
                asm volatile("ld.shared.b32 %0, [%1];" : "=r"(b0) : "r"(wrow + c0off));
                asm volatile("ld.shared.b32 %0, [%1];" : "=r"(b1) : "r"(wrow + c1off));
                mma_f16(acc[0][nt], a[0], b0, b1);
                mma_f16(acc[1][nt], a[1], b0, b1);
            }
        }

        // store batch B
        if (have) {
#pragma unroll
            for (int k = 0; k < 4; ++k)
                sts128(an + (uint32_t)(rbase + (k + 4) * 4) * A_PITCH_B + lane7 * 16, stg[k]);
        }

        if (c_cmp.tap == 8) {
            // epilogue: direct STG from accumulators
            int b  = c_cmp.tile >> 8;
            int pt = c_cmp.tile & (TILES_PER_B - 1);
            float* op = out + ((size_t)b << 23) + (size_t)pt * TILE_P;
#pragma unroll
            for (int mh = 0; mh < 2; ++mh) {
                int px = wid * 32 + mh * 16 + gid;
#pragma unroll
                for (int nt = 0; nt < 8; ++nt) {
                    int co = nt * 8 + 2 * tig;
                    float b0 = bsm[co], b1 = bsm[co + 1];
                    float* q = op + (size_t)co * HW + px;
                    q[0]      = acc[mh][nt][0] + b0;
                    q[HW]     = acc[mh][nt][1] + b1;
                    q[8]      = acc[mh][nt][2] + b0;
                    q[HW + 8] = acc[mh][nt][3] + b1;
                }
            }
        }

        adv(c_iss, gridDim.x);
        adv(c_cmp, gridDim.x);
    }
}

// ---------------------------------------------------------------------------
// Launch
// ---------------------------------------------------------------------------
extern "C" void kernel_launch(void* const* d_in, const int* in_sizes, int n_in,
                              void* d_out, int out_size) {
    const float* x    = (const float*)d_in[0];
    const void*  idx  = d_in[1];
    const float* wgt  = (const float*)d_in[2];
    const float* bias = (const float*)d_in[3];
    float* out        = (float*)d_out;

    dim3 tb(32, 8);
    dim3 tg(HW / 32, C_ / 32, B_);
    transpose_kernel<<<tg, tb>>>(x, (const unsigned int*)idx);

    cudaFuncSetAttribute(latconv_main, cudaFuncAttributeMaxDynamicSharedMemorySize,
                         SMEM_TOTAL);
    int sm_count = 0;
    cudaDeviceGetAttribute(&sm_count, cudaDevAttrMultiProcessorCount, 0);
    if (sm_count <= 0) sm_count = 148;

    latconv_main<<<sm_count, THREADS, SMEM_TOTAL>>>(idx, wgt, bias, out);
}

// round 12
// speedup vs baseline: 1.2997x; 1.0474x over previous
#include <cuda_runtime.h>
#include <cuda_fp16.h>
#include <cstdint>

// ---------------------------------------------------------------------------
// Problem constants
// ---------------------------------------------------------------------------
static constexpr int B_  = 4;
static constexpr int C_  = 64;
static constexpr int H_  = 256;
static constexpr int W_  = 512;
static constexpr int HW  = H_ * W_;               // 131072 = 2^17
static constexpr int SW_ = 3 * W_;                // 1536
static constexpr int TILE_P = 512;                // one full image row
static constexpr int TILES_PER_B = HW / TILE_P;   // 256
static constexpr int N_TILES = B_ * TILES_PER_B;  // 1024
static constexpr int THREADS = 512;               // 16 warps, 32 px/warp

// A stages: 512 px rows x 144B pitch (128B data + 16B pad, ldmatrix-friendly)
static constexpr int A_PITCH_B = 144;
static constexpr int A_BYTES   = TILE_P * A_PITCH_B;        // 73728
// W: per-thread B-fragment records: [tap][ks][lane] 64B, chunk-XOR swizzled
static constexpr int W_TAP_B   = 4 * 2048;                  // 8192 (4 ks x 32 lanes x 64B)
static constexpr int W_BYTES   = 9 * W_TAP_B;               // 73728

static constexpr int SMEM_W    = 0;
static constexpr int SMEM_BIAS = W_BYTES;                   // 256 B
static constexpr int SMEM_A    = W_BYTES + 256;             // 73984 (128-aligned)
static constexpr int SMEM_TOTAL = SMEM_A + 2 * A_BYTES;     // 221440

__device__ int    g_idx_is64;
__device__ __align__(128) __half g_xt[(size_t)B_ * HW * C_];  // [B][HW][C] fp16

// ---------------------------------------------------------------------------
// PTX helpers
// ---------------------------------------------------------------------------
__device__ __forceinline__ uint32_t smem_u32(const void* p) {
    uint32_t a;
    asm("{ .reg .u64 t; cvta.to.shared.u64 t, %1; cvt.u32.u64 %0, t; }" : "=r"(a) : "l"(p));
    return a;
}

__device__ __forceinline__ void ldmatrix_x4(uint32_t* r, uint32_t addr) {
    asm volatile("ldmatrix.sync.aligned.m8n8.x4.shared.b16 {%0,%1,%2,%3}, [%4];"
                 : "=r"(r[0]), "=r"(r[1]), "=r"(r[2]), "=r"(r[3]) : "r"(addr));
}

__device__ __forceinline__ void lds128(uint32_t* q, uint32_t addr) {
    asm volatile("ld.shared.v4.b32 {%0,%1,%2,%3}, [%4];"
                 : "=r"(q[0]), "=r"(q[1]), "=r"(q[2]), "=r"(q[3]) : "r"(addr));
}

__device__ __forceinline__ void mma_f16(float* c, const uint32_t* a, uint32_t b0, uint32_t b1) {
    asm volatile(
        "mma.sync.aligned.m16n8k16.row.col.f32.f16.f16.f32 "
        "{%0,%1,%2,%3}, {%4,%5,%6,%7}, {%8,%9}, {%0,%1,%2,%3};"
        : "+f"(c[0]), "+f"(c[1]), "+f"(c[2]), "+f"(c[3])
        : "r"(a[0]), "r"(a[1]), "r"(a[2]), "r"(a[3]), "r"(b0), "r"(b1));
}

__device__ __forceinline__ void sts128(uint32_t addr, float4 v) {
    asm volatile("st.shared.v4.b32 [%0], {%1,%2,%3,%4};"
                 :: "r"(addr), "f"(v.x), "f"(v.y), "f"(v.z), "f"(v.w) : "memory");
}

// ---------------------------------------------------------------------------
// Kernel 1: transpose x [B][C][HW] -> g_xt [B][HW][C] fp16; block (0,0,0)
//           also detects idx dtype (int64 vs int32).
// ---------------------------------------------------------------------------
__global__ void transpose_kernel(const float* __restrict__ x,
                                 const unsigned int* __restrict__ idxw) {
    if (blockIdx.x == 0 && blockIdx.y == 0 && blockIdx.z == 0 &&
        threadIdx.x == 0 && threadIdx.y == 0) {
        int is64 = 1;
        for (int i = 0; i < 64; ++i)
            if (idxw[2 * i + 1] != 0u) { is64 = 0; break; }
        g_idx_is64 = is64;
    }
    __shared__ float t[32][33];
    const int b  = blockIdx.z;
    const int cb = blockIdx.y * 32;
    const int gb = blockIdx.x * 32;
    const int tx = threadIdx.x, ty = threadIdx.y;
    const float* xb = x + (size_t)b * C_ * HW;
#pragma unroll
    for (int i = 0; i < 32; i += 8)
        t[ty + i][tx] = xb[(size_t)(cb + ty + i) * HW + gb + tx];
    __syncthreads();
    __half* xtb = g_xt + ((size_t)b * HW) * C_;
    const int c2  = tx & 15;
    const int sel = tx >> 4;
#pragma unroll
    for (int i = 0; i < 2; ++i) {
        int hwl = ty * 4 + sel * 2 + i;
        __half2 v = __floats2half2_rn(t[2 * c2][hwl], t[2 * c2 + 1][hwl]);
        *(__half2*)(xtb + (size_t)(gb + hwl) * C_ + cb + 2 * c2) = v;
    }
}

// ---------------------------------------------------------------------------
// Kernel 2: persistent fused gather (LDG.128 + STS.128, 2-stage ring,
//           software-pipelined within the step) + fp16 mma.sync.
//           tile = 512 px x 64 co.  16 warps: warp w owns px [w*32, w*32+32).
//           B fragments: one 64B record per (tap, ks, lane) -> 4x LDS.128.
// ---------------------------------------------------------------------------
struct Cur { int tile; int tap; };
__device__ __forceinline__ void adv(Cur& c, int stride) {
    if (++c.tap == 9) { c.tap = 0; c.tile += stride; }
}

// gather one 16B chunk: row's idx -> xt row base + 16B lane chunk
__device__ __forceinline__ float4 gather16(const void* idx, int is64,
                                           const Cur& c, int row, int lane7) {
    int pt = c.tile & (TILES_PER_B - 1);       // image row
    int kh = c.tap / 3;
    int kw = c.tap - kh * 3;
    int o  = (3 * pt + kh) * SW_ + 3 * row + kw;
    int g  = is64 ? (int)__ldg((const long long*)idx + o)
                  : __ldg((const int*)idx + o);
    const char* src = (const char*)g_xt
                    + ((((size_t)(c.tile >> 8)) << 17) + (uint32_t)g) * (C_ * 2)
                    + lane7 * 16;
    return __ldg((const float4*)src);
}

__global__ void __launch_bounds__(THREADS, 1)
latconv_main(const void* __restrict__ idx_raw,
             const float* __restrict__ wgt,
             const float* __restrict__ bias,
             float* __restrict__ out) {
    extern __shared__ char smem[];
    const uint32_t wbase = smem_u32(smem + SMEM_W);
    float* bsm = (float*)(smem + SMEM_BIAS);

    const int tid = threadIdx.x;
    const int wid = tid >> 5;       // 0..15
    const int lid = tid & 31;
    const int gid = lid >> 2;       // 0..7
    const int tig = lid & 3;        // 0..3
    const int is64 = g_idx_is64;
    const uint32_t bsw = (uint32_t)((lid >> 1) & 3);   // B chunk swizzle

    // gather lane mapping: 8 lanes per row -> each warp-LDG.128 covers 4 rows
    const int lane7 = lid & 7;
    const int rbase = wid * 32 + (lid >> 3);   // + k*4 for k = 0..7

    // ldmatrix per-lane address constant (16x16 A tiles, 144B pitch)
    const int lm = lid >> 3, lr = lid & 7;
    const uint32_t lconst = (uint32_t)(((lm & 1) * 8 + lr) * A_PITCH_B
                                       + (lm >> 1) * 16 + wid * 32 * A_PITCH_B);

    // Stage weights fp16 as per-thread B-fragment records.
    // For element (j, co, ci):
    //   nt = co>>3, gw = co&7 (fragment n = gid), ks = ci>>4, r = ci&15,
    //   bsel = r>>3, tw = (r&7)>>1, lo = r&1, lane = gw*4+tw,
    //   chunk c = nt>>1 (swizzled by (lane>>1)&3), u = (nt&1)*2+bsel.
    for (int e = tid; e < C_ * C_ * 9; e += THREADS) {
        int ci = e & 63, co = (e >> 6) & 63, j = e >> 12;
        int nt = co >> 3, gw = co & 7;
        int ks = ci >> 4, r = ci & 15;
        int bsel = r >> 3, tw = (r & 7) >> 1, lo = r & 1;
        int lane = gw * 4 + tw;
        int c = nt >> 1, u = ((nt & 1) << 1) + bsel;
        uint32_t off = (uint32_t)(j * W_TAP_B + ks * 2048 + lane * 64
                     + ((c ^ ((lane >> 1) & 3)) << 4) + (u << 2) + (lo << 1));
        *(__half*)(smem + SMEM_W + off) = __float2half_rn(wgt[co * 576 + ci * 9 + j]);
    }
    if (tid < C_) bsm[tid] = bias[tid];

    const uint32_t abase0 = smem_u32(smem + SMEM_A);

    const int nloc = (N_TILES - (int)blockIdx.x + (int)gridDim.x - 1) / (int)gridDim.x;
    const int S = nloc * 9;
    if (S == 0) return;

    // prologue: fill stage 0 with step-0 data
    Cur c0 = {(int)blockIdx.x, 0};
    {
#pragma unroll
        for (int k = 0; k < 8; ++k) {
            float4 v = gather16(idx_raw, is64, c0, rbase + k * 4, lane7);
            sts128(abase0 + (uint32_t)(rbase + k * 4) * A_PITCH_B + lane7 * 16, v);
        }
    }
    Cur c_iss = c0; adv(c_iss, gridDim.x);     // gathers for step s+1
    Cur c_cmp = {(int)blockIdx.x, 0};

    float acc[2][8][4];

    for (int s = 0; s < S; ++s) {
        __syncthreads();   // stage (s&1) writes visible; stage (s+1)&1 free

        const int  bc   = s & 1;
        const bool have = (s + 1 < S);
        const uint32_t ab = abase0 + bc * A_BYTES;
        const uint32_t an = abase0 + (bc ^ 1) * A_BYTES;

        // batch-A gather LDGs for step s+1 (held in regs through compute)
        float4 stg[4];
        if (have) {
#pragma unroll
            for (int k = 0; k < 4; ++k)
                stg[k] = gather16(idx_raw, is64, c_iss, rbase + k * 4, lane7);
        }

        if (c_cmp.tap == 0) {
#pragma unroll
            for (int mh = 0; mh < 2; ++mh)
#pragma unroll
                for (int nt = 0; nt < 8; ++nt)
#pragma unroll
                    for (int q = 0; q < 4; ++q) acc[mh][nt][q] = 0.f;
        }

        const uint32_t wtap = wbase + (uint32_t)c_cmp.tap * W_TAP_B
                            + (uint32_t)lid * 64;

        // compute ks = 0,1
#pragma unroll
        for (int ks = 0; ks < 2; ++ks) {
            uint32_t a[2][4];
#pragma unroll
            for (int mh = 0; mh < 2; ++mh)
                ldmatrix_x4(a[mh], ab + lconst + mh * (16 * A_PITCH_B) + ks * 32);
            const uint32_t wks = wtap + (uint32_t)ks * 2048;
#pragma unroll
            for (int c = 0; c < 4; ++c) {
                uint32_t q[4];
                lds128(q, wks + ((c ^ bsw) << 4));
                mma_f16(acc[0][2 * c],     a[0], q[0], q[1]);
                mma_f16(acc[1][2 * c],     a[1], q[0], q[1]);
                mma_f16(acc[0][2 * c + 1], a[0], q[2], q[3]);
                mma_f16(acc[1][2 * c + 1], a[1], q[2], q[3]);
            }
        }

        // store batch A, launch batch B
        if (have) {
#pragma unroll
            for (int k = 0; k < 4; ++k)
                sts128(an + (uint32_t)(rbase + k * 4) * A_PITCH_B + lane7 * 16, stg[k]);
#pragma unroll
            for (int k = 0; k < 4; ++k)
                stg[k] = gather16(idx_raw, is64, c_iss, rbase + (k + 4) * 4, lane7);
        }

        // compute ks = 2,3
#pragma unroll
        for (int ks = 2; ks < 4; ++ks) {
            uint32_t a[2][4];
#pragma unroll
            for (int mh = 0; mh < 2; ++mh)
                ldmatrix_x4(a[mh], ab + lconst + mh * (16 * A_PITCH_B) + ks * 32);
            const uint32_t wks = wtap + (uint32_t)ks * 2048;
#pragma unroll
            for (int c = 0; c < 4; ++c) {
                uint32_t q[4];
                lds128(q, wks + ((c ^ bsw) << 4));
                mma_f16(acc[0][2 * c],     a[0], q[0], q[1]);
                mma_f16(acc[1][2 * c],     a[1], q[0], q[1]);
                mma_f16(acc[0][2 * c + 1], a[0], q[2], q[3]);
                mma_f16(acc[1][2 * c + 1], a[1], q[2], q[3]);
            }
        }

        // store batch B
        if (have) {
#pragma unroll
            for (int k = 0; k < 4; ++k)
                sts128(an + (uint32_t)(rbase + (k + 4) * 4) * A_PITCH_B + lane7 * 16, stg[k]);
        }

        if (c_cmp.tap == 8) {
            // epilogue: direct STG from accumulators
            int b  = c_cmp.tile >> 8;
            int pt = c_cmp.tile & (TILES_PER_B - 1);
            float* op = out + ((size_t)b << 23) + (size_t)pt * TILE_P;
#pragma unroll
            for (int mh = 0; mh < 2; ++mh) {
                int px = wid * 32 + mh * 16 + gid;
#pragma unroll
                for (int nt = 0; nt < 8; ++nt) {
                    int co = nt * 8 + 2 * tig;
                    float b0 = bsm[co], b1 = bsm[co + 1];
                    float* q = op + (size_t)co * HW + px;
                    q[0]      = acc[mh][nt][0] + b0;
                    q[HW]     = acc[mh][nt][1] + b1;
                    q[8]      = acc[mh][nt][2] + b0;
                    q[HW + 8] = acc[mh][nt][3] + b1;
                }
            }
        }

        adv(c_iss, gridDim.x);
        adv(c_cmp, gridDim.x);
    }
}

// ---------------------------------------------------------------------------
// Launch
// ---------------------------------------------------------------------------
extern "C" void kernel_launch(void* const* d_in, const int* in_sizes, int n_in,
                              void* d_out, int out_size) {
    const float* x    = (const float*)d_in[0];
    const void*  idx  = d_in[1];
    const float* wgt  = (const float*)d_in[2];
    const float* bias = (const float*)d_in[3];
    float* out        = (float*)d_out;

    dim3 tb(32, 8);
    dim3 tg(HW / 32, C_ / 32, B_);
    transpose_kernel<<<tg, tb>>>(x, (const unsigned int*)idx);

    cudaFuncSetAttribute(latconv_main, cudaFuncAttributeMaxDynamicSharedMemorySize,
                         SMEM_TOTAL);
    int sm_count = 0;
    cudaDeviceGetAttribute(&sm_count, cudaDevAttrMultiProcessorCount, 0);
    if (sm_count <= 0) sm_count = 148;

    latconv_main<<<sm_count, THREADS, SMEM_TOTAL>>>(idx, wgt, bias, out);
}